// round 4
// baseline (speedup 1.0000x reference)
#include <cuda_runtime.h>
#include <cuda_bf16.h>

#define NN 50000
#define EE 800000
#define F_IN 64
#define F_HID 128
#define F_OUT 64

// ---------------- device scratch (no allocations allowed) ----------------
// NOTE: __align__(16) is load-bearing — these are accessed via float4.
__device__ __align__(16) int   g_outdeg[NN];
__device__ __align__(16) int   g_indeg[NN];
__device__ __align__(16) int   g_cursor[NN];
__device__ __align__(16) int   g_rowptr[NN + 1];
__device__ __align__(16) int   g_esrc[EE];
__device__ __align__(16) float g_norm_src[NN];
__device__ __align__(16) float g_norm_dst[NN];
__device__ __align__(16) float g_agg1[(size_t)NN * F_IN];
__device__ __align__(16) float g_h1[(size_t)NN * F_HID];
__device__ __align__(16) float g_h2[(size_t)NN * F_OUT];

// ---------------- graph preprocessing ----------------
__global__ void k_zero() {
    int i = blockIdx.x * blockDim.x + threadIdx.x;
    if (i < NN) { g_outdeg[i] = 0; g_indeg[i] = 0; g_cursor[i] = 0; }
}

__global__ void k_degree(const int* __restrict__ src,
                         const int* __restrict__ dst) {
    int e = blockIdx.x * blockDim.x + threadIdx.x;
    if (e < EE) {
        atomicAdd(&g_outdeg[src[e]], 1);
        atomicAdd(&g_indeg[dst[e]], 1);
    }
}

__global__ void k_norm() {
    int i = blockIdx.x * blockDim.x + threadIdx.x;
    if (i < NN) {
        g_norm_src[i] = rsqrtf((float)max(g_outdeg[i], 1));
        g_norm_dst[i] = rsqrtf((float)max(g_indeg[i], 1));
    }
}

// single-block exclusive scan of indeg -> rowptr
__global__ void k_scan() {
    __shared__ int sh[1024];
    __shared__ int carry;
    int t = threadIdx.x;
    if (t == 0) { g_rowptr[0] = 0; carry = 0; }
    __syncthreads();
    for (int base = 0; base < NN; base += 1024) {
        int v = (base + t < NN) ? g_indeg[base + t] : 0;
        sh[t] = v;
        __syncthreads();
        for (int off = 1; off < 1024; off <<= 1) {
            int x = (t >= off) ? sh[t - off] : 0;
            __syncthreads();
            sh[t] += x;
            __syncthreads();
        }
        if (base + t < NN) g_rowptr[base + t + 1] = carry + sh[t];
        __syncthreads();
        if (t == 0) carry += sh[1023];
        __syncthreads();
    }
}

__global__ void k_scatter(const int* __restrict__ src,
                          const int* __restrict__ dst) {
    int e = blockIdx.x * blockDim.x + threadIdx.x;
    if (e < EE) {
        int d = dst[e];
        int pos = g_rowptr[d] + atomicAdd(&g_cursor[d], 1);
        g_esrc[pos] = src[e];
    }
}

// ---------------- aggregation: one 64-thread block per destination node ----------------
// LAYER1: feat = x (arg), scale each gathered row by norm_src[u], out = g_agg1 (internal)
// !LAYER1: feat = g_h2 (internal), out = arg, epilogue out = acc*norm_dst + bias
template <bool LAYER1>
__global__ void k_agg(const float* __restrict__ feat_in,
                      const float* __restrict__ bias,
                      float* __restrict__ out_arg) {
    const float* __restrict__ feat = LAYER1 ? feat_in : (const float*)g_h2;
    int n = blockIdx.x;
    int f = threadIdx.x;                 // 0..63
    int s = g_rowptr[n], e = g_rowptr[n + 1];
    float acc = 0.f;
    for (int j = s; j < e; j++) {
        int u = g_esrc[j];
        float v = feat[(size_t)u * 64 + f];
        if (LAYER1) v *= g_norm_src[u];
        acc += v;
    }
    if (LAYER1) g_agg1[(size_t)n * 64 + f] = acc;
    else        out_arg[(size_t)n * 64 + f] = fmaf(acc, g_norm_dst[n], bias[f]);
}

// ---------------- GEMM 1: h1 = relu((agg1 @ W1) * norm_dst + b1) ----------------
// agg1: [N,64], W1: [64,128], h1: [N,128]. Block = 64 rows x 128 cols, 256 threads.
__global__ void __launch_bounds__(256) k_gemm1(const float* __restrict__ W1,
                                               const float* __restrict__ b1) {
    __shared__ float As[64][64];    // transposed: As[k][r]
    __shared__ float Ws[64][128];   // Ws[k][c]
    int tid  = threadIdx.x;
    int row0 = blockIdx.x * 64;

    // A tile (transposed store)
    #pragma unroll
    for (int i = tid; i < 64 * 64 / 4; i += 256) {
        int idx = i * 4;
        int r = idx >> 6, k = idx & 63;
        float4 v = make_float4(0.f, 0.f, 0.f, 0.f);
        int row = row0 + r;
        if (row < NN) v = *reinterpret_cast<const float4*>(&g_agg1[(size_t)row * 64 + k]);
        As[k][r] = v.x; As[k + 1][r] = v.y; As[k + 2][r] = v.z; As[k + 3][r] = v.w;
    }
    // W tile
    #pragma unroll
    for (int i = tid; i < 64 * 128 / 4; i += 256) {
        int idx = i * 4;
        int k = idx >> 7, c = idx & 127;
        *reinterpret_cast<float4*>(&Ws[k][c]) =
            *reinterpret_cast<const float4*>(&W1[idx]);
    }
    __syncthreads();

    int tx = tid & 15;   // 16 col-groups of 8
    int ty = tid >> 4;   // 16 row-groups of 4
    float acc[4][8];
    #pragma unroll
    for (int i = 0; i < 4; i++)
        #pragma unroll
        for (int j = 0; j < 8; j++) acc[i][j] = 0.f;

    #pragma unroll 8
    for (int k = 0; k < 64; k++) {
        float a[4];
        #pragma unroll
        for (int i = 0; i < 4; i++) a[i] = As[k][ty * 4 + i];
        float4 w0 = *reinterpret_cast<float4*>(&Ws[k][tx * 8]);
        float4 w1 = *reinterpret_cast<float4*>(&Ws[k][tx * 8 + 4]);
        float w[8] = {w0.x, w0.y, w0.z, w0.w, w1.x, w1.y, w1.z, w1.w};
        #pragma unroll
        for (int i = 0; i < 4; i++)
            #pragma unroll
            for (int j = 0; j < 8; j++)
                acc[i][j] = fmaf(a[i], w[j], acc[i][j]);
    }

    // epilogue: relu(acc * norm_dst[row] + b1[c])
    float4 bv0 = *reinterpret_cast<const float4*>(&b1[tx * 8]);
    float4 bv1 = *reinterpret_cast<const float4*>(&b1[tx * 8 + 4]);
    float bb[8] = {bv0.x, bv0.y, bv0.z, bv0.w, bv1.x, bv1.y, bv1.z, bv1.w};
    #pragma unroll
    for (int i = 0; i < 4; i++) {
        int row = row0 + ty * 4 + i;
        if (row >= NN) break;
        float nd = g_norm_dst[row];
        float r_[8];
        #pragma unroll
        for (int j = 0; j < 8; j++) r_[j] = fmaxf(fmaf(acc[i][j], nd, bb[j]), 0.f);
        float* hp = &g_h1[(size_t)row * 128 + tx * 8];
        *reinterpret_cast<float4*>(hp)     = make_float4(r_[0], r_[1], r_[2], r_[3]);
        *reinterpret_cast<float4*>(hp + 4) = make_float4(r_[4], r_[5], r_[6], r_[7]);
    }
}

// ---------------- GEMM 2: h2 = (h1 * norm_src) @ W2 ----------------
// h1: [N,128], W2: [128,64], h2: [N,64]. Block = 64 rows x 64 cols, K split 2x64.
__global__ void __launch_bounds__(256) k_gemm2(const float* __restrict__ W2) {
    __shared__ float As[64][64];   // [k_local][r]
    __shared__ float Ws[64][64];   // [k_local][c]
    __shared__ float ns[64];
    int tid  = threadIdx.x;
    int row0 = blockIdx.x * 64;

    if (tid < 64) {
        int row = row0 + tid;
        ns[tid] = (row < NN) ? g_norm_src[row] : 0.f;
    }

    int tx = tid & 15;   // 16 col-groups of 4
    int ty = tid >> 4;   // 16 row-groups of 4
    float acc[4][4];
    #pragma unroll
    for (int i = 0; i < 4; i++)
        #pragma unroll
        for (int j = 0; j < 4; j++) acc[i][j] = 0.f;

    for (int kc = 0; kc < 128; kc += 64) {
        __syncthreads();   // also covers ns on first pass
        #pragma unroll
        for (int i = tid; i < 64 * 64 / 4; i += 256) {
            int idx = i * 4;
            int r = idx >> 6, k = idx & 63;
            float4 v = make_float4(0.f, 0.f, 0.f, 0.f);
            int row = row0 + r;
            if (row < NN) v = *reinterpret_cast<const float4*>(&g_h1[(size_t)row * 128 + kc + k]);
            float s = ns[r];
            As[k][r] = v.x * s; As[k + 1][r] = v.y * s;
            As[k + 2][r] = v.z * s; As[k + 3][r] = v.w * s;
        }
        #pragma unroll
        for (int i = tid; i < 64 * 64 / 4; i += 256) {
            int idx = i * 4;
            int k = idx >> 6, c = idx & 63;
            *reinterpret_cast<float4*>(&Ws[k][c]) =
                *reinterpret_cast<const float4*>(&W2[(size_t)(kc + k) * 64 + c]);
        }
        __syncthreads();

        #pragma unroll 8
        for (int k = 0; k < 64; k++) {
            float a[4];
            #pragma unroll
            for (int i = 0; i < 4; i++) a[i] = As[k][ty * 4 + i];
            float4 w4 = *reinterpret_cast<float4*>(&Ws[k][tx * 4]);
            float w[4] = {w4.x, w4.y, w4.z, w4.w};
            #pragma unroll
            for (int i = 0; i < 4; i++)
                #pragma unroll
                for (int j = 0; j < 4; j++)
                    acc[i][j] = fmaf(a[i], w[j], acc[i][j]);
        }
    }

    #pragma unroll
    for (int i = 0; i < 4; i++) {
        int row = row0 + ty * 4 + i;
        if (row >= NN) break;
        *reinterpret_cast<float4*>(&g_h2[(size_t)row * 64 + tx * 4]) =
            make_float4(acc[i][0], acc[i][1], acc[i][2], acc[i][3]);
    }
}

// ---------------- launch ----------------
extern "C" void kernel_launch(void* const* d_in, const int* in_sizes, int n_in,
                              void* d_out, int out_size) {
    const float* x   = (const float*)d_in[0];
    const float* W1  = (const float*)d_in[1];
    const float* b1  = (const float*)d_in[2];
    const float* W2  = (const float*)d_in[3];
    const float* b2  = (const float*)d_in[4];
    const int*   src = (const int*)d_in[5];   // JAX default x64-disabled: int32!
    const int*   dst = (const int*)d_in[6];
    float* out = (float*)d_out;

    k_zero<<<(NN + 255) / 256, 256>>>();
    k_degree<<<(EE + 255) / 256, 256>>>(src, dst);
    k_norm<<<(NN + 255) / 256, 256>>>();
    k_scan<<<1, 1024>>>();
    k_scatter<<<(EE + 255) / 256, 256>>>(src, dst);

    // layer 1: agg (scaled by norm_src at gather) -> GEMM1 (+norm_dst, +b1, relu)
    k_agg<true><<<NN, 64>>>(x, nullptr, nullptr);
    k_gemm1<<<(NN + 63) / 64, 256>>>(W1, b1);

    // layer 2: GEMM2 (norm_src folded into A-load) -> agg (+norm_dst, +b2) -> out
    k_gemm2<<<(NN + 63) / 64, 256>>>(W2);
    k_agg<false><<<NN, 64>>>(nullptr, b2, out);
}

// round 5
// speedup vs baseline: 1.3509x; 1.3509x over previous
#include <cuda_runtime.h>
#include <cuda_bf16.h>

#define NN 50000
#define EE 800000
#define F_IN 64
#define F_HID 128
#define F_OUT 64
#define SCAN_BLK ((NN + 1023) / 1024)   // 49

// ---------------- device scratch (no allocations allowed) ----------------
// NOTE: __align__(16) is load-bearing — these are accessed via float4.
__device__ __align__(16) int   g_outdeg[NN];
__device__ __align__(16) int   g_indeg[NN];
__device__ __align__(16) int   g_cursor[NN];
__device__ __align__(16) int   g_rowptr[NN + 1];
__device__ __align__(16) int   g_esrc[EE];
__device__ __align__(16) int   g_bsum[SCAN_BLK];
__device__ __align__(16) int   g_boff[SCAN_BLK];
__device__ __align__(16) float g_norm_src[NN];
__device__ __align__(16) float g_norm_dst[NN];
__device__ __align__(16) float g_agg1[(size_t)NN * F_IN];
__device__ __align__(16) float g_h1[(size_t)NN * F_HID];
__device__ __align__(16) float g_h2[(size_t)NN * F_OUT];

// ---------------- graph preprocessing ----------------
__global__ void k_zero() {
    int i = blockIdx.x * blockDim.x + threadIdx.x;
    if (i < NN) { g_outdeg[i] = 0; g_indeg[i] = 0; g_cursor[i] = 0; }
}

__global__ void k_degree(const int* __restrict__ src,
                         const int* __restrict__ dst) {
    int e = blockIdx.x * blockDim.x + threadIdx.x;
    if (e < EE) {
        atomicAdd(&g_outdeg[src[e]], 1);
        atomicAdd(&g_indeg[dst[e]], 1);
    }
}

__global__ void k_norm() {
    int i = blockIdx.x * blockDim.x + threadIdx.x;
    if (i < NN) {
        g_norm_src[i] = rsqrtf((float)max(g_outdeg[i], 1));
        g_norm_dst[i] = rsqrtf((float)max(g_indeg[i], 1));
    }
}

// ---------------- 3-phase multi-block scan of indeg -> rowptr ----------------
// Phase 1: per-block inclusive scan (49 concurrent blocks)
__global__ void k_scan_blk() {
    __shared__ int sh[1024];
    int t = threadIdx.x;
    int i = blockIdx.x * 1024 + t;
    sh[t] = (i < NN) ? g_indeg[i] : 0;
    __syncthreads();
    #pragma unroll
    for (int off = 1; off < 1024; off <<= 1) {
        int x = (t >= off) ? sh[t - off] : 0;
        __syncthreads();
        sh[t] += x;
        __syncthreads();
    }
    if (i < NN) g_rowptr[i + 1] = sh[t];
    if (t == 1023) g_bsum[blockIdx.x] = sh[1023];
}

// Phase 2: exclusive scan of the 49 block sums (tiny)
__global__ void k_scan_top() {
    __shared__ int sh[SCAN_BLK];
    int t = threadIdx.x;
    if (t < SCAN_BLK) sh[t] = g_bsum[t];
    __syncthreads();
    if (t == 0) {
        int acc = 0;
        for (int b = 0; b < SCAN_BLK; b++) { int tmp = sh[b]; sh[b] = acc; acc += tmp; }
        g_rowptr[0] = 0;
    }
    __syncthreads();
    if (t < SCAN_BLK) g_boff[t] = sh[t];
}

// Phase 3: add block offsets
__global__ void k_scan_add() {
    int i = blockIdx.x * blockDim.x + threadIdx.x;
    if (i < NN) g_rowptr[i + 1] += g_boff[i >> 10];
}

__global__ void k_scatter(const int* __restrict__ src,
                          const int* __restrict__ dst) {
    int e = blockIdx.x * blockDim.x + threadIdx.x;
    if (e < EE) {
        int d = dst[e];
        int pos = g_rowptr[d] + atomicAdd(&g_cursor[d], 1);
        g_esrc[pos] = src[e];
    }
}

// ---------------- aggregation: one 64-thread block per destination node ----------------
// LAYER1: feat = x (arg), scale each gathered row by norm_src[u], out = g_agg1 (internal)
// !LAYER1: feat = g_h2 (internal), out = arg, epilogue out = acc*norm_dst + bias
template <bool LAYER1>
__global__ void k_agg(const float* __restrict__ feat_in,
                      const float* __restrict__ bias,
                      float* __restrict__ out_arg) {
    const float* __restrict__ feat = LAYER1 ? feat_in : (const float*)g_h2;
    int n = blockIdx.x;
    int f = threadIdx.x;                 // 0..63
    int s = g_rowptr[n], e = g_rowptr[n + 1];
    float acc = 0.f;
    for (int j = s; j < e; j++) {
        int u = g_esrc[j];
        float v = feat[(size_t)u * 64 + f];
        if (LAYER1) v *= g_norm_src[u];
        acc += v;
    }
    if (LAYER1) g_agg1[(size_t)n * 64 + f] = acc;
    else        out_arg[(size_t)n * 64 + f] = fmaf(acc, g_norm_dst[n], bias[f]);
}

// ---------------- GEMM 1: h1 = relu((agg1 @ W1) * norm_dst + b1) ----------------
// agg1: [N,64], W1: [64,128], h1: [N,128]. Block = 64 rows x 128 cols, 256 threads.
__global__ void __launch_bounds__(256) k_gemm1(const float* __restrict__ W1,
                                               const float* __restrict__ b1) {
    __shared__ float As[64][64];    // transposed: As[k][r]
    __shared__ float Ws[64][128];   // Ws[k][c]
    int tid  = threadIdx.x;
    int row0 = blockIdx.x * 64;

    // A tile (transposed store)
    #pragma unroll
    for (int i = tid; i < 64 * 64 / 4; i += 256) {
        int idx = i * 4;
        int r = idx >> 6, k = idx & 63;
        float4 v = make_float4(0.f, 0.f, 0.f, 0.f);
        int row = row0 + r;
        if (row < NN) v = *reinterpret_cast<const float4*>(&g_agg1[(size_t)row * 64 + k]);
        As[k][r] = v.x; As[k + 1][r] = v.y; As[k + 2][r] = v.z; As[k + 3][r] = v.w;
    }
    // W tile
    #pragma unroll
    for (int i = tid; i < 64 * 128 / 4; i += 256) {
        int idx = i * 4;
        int k = idx >> 7, c = idx & 127;
        *reinterpret_cast<float4*>(&Ws[k][c]) =
            *reinterpret_cast<const float4*>(&W1[idx]);
    }
    __syncthreads();

    int tx = tid & 15;   // 16 col-groups of 8
    int ty = tid >> 4;   // 16 row-groups of 4
    float acc[4][8];
    #pragma unroll
    for (int i = 0; i < 4; i++)
        #pragma unroll
        for (int j = 0; j < 8; j++) acc[i][j] = 0.f;

    #pragma unroll 8
    for (int k = 0; k < 64; k++) {
        float a[4];
        #pragma unroll
        for (int i = 0; i < 4; i++) a[i] = As[k][ty * 4 + i];
        float4 w0 = *reinterpret_cast<float4*>(&Ws[k][tx * 8]);
        float4 w1 = *reinterpret_cast<float4*>(&Ws[k][tx * 8 + 4]);
        float w[8] = {w0.x, w0.y, w0.z, w0.w, w1.x, w1.y, w1.z, w1.w};
        #pragma unroll
        for (int i = 0; i < 4; i++)
            #pragma unroll
            for (int j = 0; j < 8; j++)
                acc[i][j] = fmaf(a[i], w[j], acc[i][j]);
    }

    // epilogue: relu(acc * norm_dst[row] + b1[c])
    float4 bv0 = *reinterpret_cast<const float4*>(&b1[tx * 8]);
    float4 bv1 = *reinterpret_cast<const float4*>(&b1[tx * 8 + 4]);
    float bb[8] = {bv0.x, bv0.y, bv0.z, bv0.w, bv1.x, bv1.y, bv1.z, bv1.w};
    #pragma unroll
    for (int i = 0; i < 4; i++) {
        int row = row0 + ty * 4 + i;
        if (row >= NN) break;
        float nd = g_norm_dst[row];
        float r_[8];
        #pragma unroll
        for (int j = 0; j < 8; j++) r_[j] = fmaxf(fmaf(acc[i][j], nd, bb[j]), 0.f);
        float* hp = &g_h1[(size_t)row * 128 + tx * 8];
        *reinterpret_cast<float4*>(hp)     = make_float4(r_[0], r_[1], r_[2], r_[3]);
        *reinterpret_cast<float4*>(hp + 4) = make_float4(r_[4], r_[5], r_[6], r_[7]);
    }
}

// ---------------- GEMM 2: h2 = (h1 * norm_src) @ W2 ----------------
// h1: [N,128], W2: [128,64], h2: [N,64]. Block = 64 rows x 64 cols, K split 2x64.
__global__ void __launch_bounds__(256) k_gemm2(const float* __restrict__ W2) {
    __shared__ float As[64][64];   // [k_local][r]
    __shared__ float Ws[64][64];   // [k_local][c]
    __shared__ float ns[64];
    int tid  = threadIdx.x;
    int row0 = blockIdx.x * 64;

    if (tid < 64) {
        int row = row0 + tid;
        ns[tid] = (row < NN) ? g_norm_src[row] : 0.f;
    }

    int tx = tid & 15;   // 16 col-groups of 4
    int ty = tid >> 4;   // 16 row-groups of 4
    float acc[4][4];
    #pragma unroll
    for (int i = 0; i < 4; i++)
        #pragma unroll
        for (int j = 0; j < 4; j++) acc[i][j] = 0.f;

    for (int kc = 0; kc < 128; kc += 64) {
        __syncthreads();   // also covers ns on first pass
        #pragma unroll
        for (int i = tid; i < 64 * 64 / 4; i += 256) {
            int idx = i * 4;
            int r = idx >> 6, k = idx & 63;
            float4 v = make_float4(0.f, 0.f, 0.f, 0.f);
            int row = row0 + r;
            if (row < NN) v = *reinterpret_cast<const float4*>(&g_h1[(size_t)row * 128 + kc + k]);
            float s = ns[r];
            As[k][r] = v.x * s; As[k + 1][r] = v.y * s;
            As[k + 2][r] = v.z * s; As[k + 3][r] = v.w * s;
        }
        #pragma unroll
        for (int i = tid; i < 64 * 64 / 4; i += 256) {
            int idx = i * 4;
            int k = idx >> 6, c = idx & 63;
            *reinterpret_cast<float4*>(&Ws[k][c]) =
                *reinterpret_cast<const float4*>(&W2[(size_t)(kc + k) * 64 + c]);
        }
        __syncthreads();

        #pragma unroll 8
        for (int k = 0; k < 64; k++) {
            float a[4];
            #pragma unroll
            for (int i = 0; i < 4; i++) a[i] = As[k][ty * 4 + i];
            float4 w4 = *reinterpret_cast<float4*>(&Ws[k][tx * 4]);
            float w[4] = {w4.x, w4.y, w4.z, w4.w};
            #pragma unroll
            for (int i = 0; i < 4; i++)
                #pragma unroll
                for (int j = 0; j < 4; j++)
                    acc[i][j] = fmaf(a[i], w[j], acc[i][j]);
        }
    }

    #pragma unroll
    for (int i = 0; i < 4; i++) {
        int row = row0 + ty * 4 + i;
        if (row >= NN) break;
        *reinterpret_cast<float4*>(&g_h2[(size_t)row * 64 + tx * 4]) =
            make_float4(acc[i][0], acc[i][1], acc[i][2], acc[i][3]);
    }
}

// ---------------- launch ----------------
extern "C" void kernel_launch(void* const* d_in, const int* in_sizes, int n_in,
                              void* d_out, int out_size) {
    const float* x   = (const float*)d_in[0];
    const float* W1  = (const float*)d_in[1];
    const float* b1  = (const float*)d_in[2];
    const float* W2  = (const float*)d_in[3];
    const float* b2  = (const float*)d_in[4];
    const int*   src = (const int*)d_in[5];   // JAX default x64-disabled: int32
    const int*   dst = (const int*)d_in[6];
    float* out = (float*)d_out;

    k_zero<<<(NN + 255) / 256, 256>>>();
    k_degree<<<(EE + 255) / 256, 256>>>(src, dst);
    k_norm<<<(NN + 255) / 256, 256>>>();
    k_scan_blk<<<SCAN_BLK, 1024>>>();
    k_scan_top<<<1, 64>>>();
    k_scan_add<<<(NN + 255) / 256, 256>>>();
    k_scatter<<<(EE + 255) / 256, 256>>>(src, dst);

    // layer 1: agg (scaled by norm_src at gather) -> GEMM1 (+norm_dst, +b1, relu)
    k_agg<true><<<NN, 64>>>(x, nullptr, nullptr);
    k_gemm1<<<(NN + 63) / 64, 256>>>(W1, b1);

    // layer 2: GEMM2 (norm_src folded into A-load) -> agg (+norm_dst, +b2) -> out
    k_gemm2<<<(NN + 63) / 64, 256>>>(W2);
    k_agg<false><<<NN, 64>>>(nullptr, b2, out);
}

// round 7
// speedup vs baseline: 1.9849x; 1.4693x over previous
#include <cuda_runtime.h>
#include <cuda_bf16.h>
#include <cstdint>

#define NN 50000
#define EE 800000
#define F_IN 64
#define F_HID 128
#define F_OUT 64
#define SCAN_BLK ((NN + 1023) / 1024)   // 49

// ---------------- device scratch (no allocations allowed) ----------------
__device__ __align__(16) int   g_outdeg[NN];
__device__ __align__(16) int   g_indeg[NN];
__device__ __align__(16) int   g_cursor[NN];
__device__ __align__(16) int   g_rowptr[NN + 1];
__device__ __align__(16) int   g_esrc[EE];
__device__ __align__(16) int   g_bsum[SCAN_BLK];
__device__ __align__(16) float g_norm_src[NN];
__device__ __align__(16) float g_norm_dst[NN];
__device__ __align__(16) float g_agg1[(size_t)NN * F_IN];
__device__ __align__(16) float g_h1[(size_t)NN * F_HID];
__device__ __align__(16) float g_h2[(size_t)NN * F_OUT];

__device__ __forceinline__ uint32_t f2tf32(float v) {
    uint32_t u;
    asm("cvt.rna.tf32.f32 %0, %1;" : "=r"(u) : "f"(v));
    return u;
}

#define MMA_TF32(c0, c1, c2, c3, a0, a1, a2, a3, b0, b1) \
    asm volatile("mma.sync.aligned.m16n8k8.row.col.f32.tf32.tf32.f32 " \
        "{%0,%1,%2,%3}, {%4,%5,%6,%7}, {%8,%9}, {%0,%1,%2,%3};" \
        : "+f"(c0), "+f"(c1), "+f"(c2), "+f"(c3) \
        : "r"(a0), "r"(a1), "r"(a2), "r"(a3), "r"(b0), "r"(b1))

// ---------------- graph preprocessing ----------------
__global__ void k_zero() {
    int i = blockIdx.x * blockDim.x + threadIdx.x;
    if (i < NN) { g_outdeg[i] = 0; g_indeg[i] = 0; }
}

__global__ void k_degree(const int* __restrict__ src, const int* __restrict__ dst) {
    int e = blockIdx.x * blockDim.x + threadIdx.x;
    if (e < EE) {
        atomicAdd(&g_outdeg[src[e]], 1);
        atomicAdd(&g_indeg[dst[e]], 1);
    }
}

// per-block inclusive scan of indeg; norms fused
__global__ void k_scan_blk() {
    __shared__ int sh[1024];
    int t = threadIdx.x;
    int i = blockIdx.x * 1024 + t;
    int deg = (i < NN) ? g_indeg[i] : 0;
    if (i < NN) {
        g_norm_dst[i] = rsqrtf((float)max(deg, 1));
        g_norm_src[i] = rsqrtf((float)max(g_outdeg[i], 1));
    }
    sh[t] = deg;
    __syncthreads();
    #pragma unroll
    for (int off = 1; off < 1024; off <<= 1) {
        int x = (t >= off) ? sh[t - off] : 0;
        __syncthreads();
        sh[t] += x;
        __syncthreads();
    }
    if (i < NN) g_rowptr[i + 1] = sh[t];
    if (t == 1023) g_bsum[blockIdx.x] = sh[1023];
}

// add block offsets (warp-computed bsum prefix) + cursor init fused
__global__ void k_scan_add() {
    __shared__ int off;
    int t = threadIdx.x;
    int i = blockIdx.x * 256 + t;
    if (t < 32) {
        int c = (blockIdx.x * 256) >> 10;   // constant within block
        int s = 0;
        for (int b = t; b < c; b += 32) s += g_bsum[b];
        #pragma unroll
        for (int o = 16; o > 0; o >>= 1) s += __shfl_down_sync(0xFFFFFFFFu, s, o);
        if (t == 0) off = s;
    }
    __syncthreads();
    if (i < NN) {
        int v = g_rowptr[i + 1] + off;
        g_rowptr[i + 1] = v;
        if (i + 1 < NN) g_cursor[i + 1] = v;
        if (i == 0) { g_rowptr[0] = 0; g_cursor[0] = 0; }
    }
}

__global__ void k_scatter(const int* __restrict__ src, const int* __restrict__ dst) {
    int e = blockIdx.x * blockDim.x + threadIdx.x;
    if (e < EE) {
        int pos = atomicAdd(&g_cursor[dst[e]], 1);
        g_esrc[pos] = src[e];
    }
}

// ---------------- aggregation: one 64-thread block per destination node ----------------
template <bool LAYER1>
__global__ void k_agg(const float* __restrict__ feat_in,
                      const float* __restrict__ bias,
                      float* __restrict__ out_arg) {
    const float* __restrict__ feat = LAYER1 ? feat_in : (const float*)g_h2;
    int n = blockIdx.x;
    int f = threadIdx.x;
    int s = g_rowptr[n], e = g_rowptr[n + 1];
    float acc = 0.f;
    for (int j = s; j < e; j++) {
        int u = g_esrc[j];
        float v = feat[(size_t)u * 64 + f];
        if (LAYER1) v *= g_norm_src[u];
        acc += v;
    }
    if (LAYER1) g_agg1[(size_t)n * 64 + f] = acc;
    else        out_arg[(size_t)n * 64 + f] = fmaf(acc, g_norm_dst[n], bias[f]);
}

// ---------------- GEMM 1 (tf32 mma.sync): h1 = relu((agg1 @ W1)*nd + b1) ----------------
// Block tile 128x128, K=64. 8 warps as 4(row)x2(col): each warp 32r x 64c.
// dyn smem: As[128][76] | Ws[64][132] | sb1[128]
#define G1_AS_STRIDE 76
#define G1_WS_STRIDE 132
#define G1_WS_OFF  (128 * G1_AS_STRIDE)
#define G1_B1_OFF  (G1_WS_OFF + 64 * G1_WS_STRIDE)
#define G1_SMEM    ((G1_B1_OFF + 128) * 4)

__global__ void __launch_bounds__(256) k_gemm1_mma(const float* __restrict__ W1,
                                                   const float* __restrict__ b1) {
    extern __shared__ float sm[];
    float* As  = sm;
    float* Ws  = sm + G1_WS_OFF;
    float* sb1 = sm + G1_B1_OFF;

    int tid = threadIdx.x;
    int row0 = blockIdx.x * 128;

    // A tile: 128x64, tf32-rounded
    #pragma unroll
    for (int it = 0; it < 8; it++) {
        int idx4 = tid + it * 256;           // [0,2048)
        int r = idx4 >> 4, c4 = idx4 & 15;
        float4 v = make_float4(0.f, 0.f, 0.f, 0.f);
        int row = row0 + r;
        if (row < NN) v = *reinterpret_cast<const float4*>(&g_agg1[(size_t)row * 64 + c4 * 4]);
        float* p = &As[r * G1_AS_STRIDE + c4 * 4];
        p[0] = __uint_as_float(f2tf32(v.x)); p[1] = __uint_as_float(f2tf32(v.y));
        p[2] = __uint_as_float(f2tf32(v.z)); p[3] = __uint_as_float(f2tf32(v.w));
    }
    // W tile: 64x128
    #pragma unroll
    for (int it = 0; it < 8; it++) {
        int idx4 = tid + it * 256;           // [0,2048)
        int k = idx4 >> 5, c4 = idx4 & 31;
        float4 v = *reinterpret_cast<const float4*>(&W1[(size_t)k * 128 + c4 * 4]);
        float* p = &Ws[k * G1_WS_STRIDE + c4 * 4];
        p[0] = __uint_as_float(f2tf32(v.x)); p[1] = __uint_as_float(f2tf32(v.y));
        p[2] = __uint_as_float(f2tf32(v.z)); p[3] = __uint_as_float(f2tf32(v.w));
    }
    if (tid < 128) sb1[tid] = b1[tid];
    __syncthreads();

    int w = tid >> 5, lane = tid & 31;
    int wr = w >> 1, wc = w & 1;             // 4x2 warp grid
    int g = lane >> 2, t4 = lane & 3;

    float c[2][8][4];
    #pragma unroll
    for (int i = 0; i < 2; i++)
        #pragma unroll
        for (int j = 0; j < 8; j++)
            #pragma unroll
            for (int q = 0; q < 4; q++) c[i][j][q] = 0.f;

    const uint32_t* Au = reinterpret_cast<const uint32_t*>(As);
    const uint32_t* Wu = reinterpret_cast<const uint32_t*>(Ws);

    #pragma unroll
    for (int ks = 0; ks < 8; ks++) {
        int kb = ks * 8;
        uint32_t a[2][4];
        #pragma unroll
        for (int rf = 0; rf < 2; rf++) {
            int R = wr * 32 + rf * 16;
            a[rf][0] = Au[(R + g) * G1_AS_STRIDE + kb + t4];
            a[rf][1] = Au[(R + 8 + g) * G1_AS_STRIDE + kb + t4];
            a[rf][2] = Au[(R + g) * G1_AS_STRIDE + kb + 4 + t4];
            a[rf][3] = Au[(R + 8 + g) * G1_AS_STRIDE + kb + 4 + t4];
        }
        #pragma unroll
        for (int cf = 0; cf < 8; cf++) {
            int C = wc * 64 + cf * 8 + g;
            uint32_t b0 = Wu[(kb + t4) * G1_WS_STRIDE + C];
            uint32_t b1r = Wu[(kb + 4 + t4) * G1_WS_STRIDE + C];
            #pragma unroll
            for (int rf = 0; rf < 2; rf++)
                MMA_TF32(c[rf][cf][0], c[rf][cf][1], c[rf][cf][2], c[rf][cf][3],
                         a[rf][0], a[rf][1], a[rf][2], a[rf][3], b0, b1r);
        }
    }

    // epilogue: relu(c * nd + b1), float2 stores (cols 2t4, 2t4+1 contiguous)
    #pragma unroll
    for (int rf = 0; rf < 2; rf++) {
        int r1 = row0 + wr * 32 + rf * 16 + g;
        int r2 = r1 + 8;
        float nd1 = (r1 < NN) ? g_norm_dst[r1] : 0.f;
        float nd2 = (r2 < NN) ? g_norm_dst[r2] : 0.f;
        #pragma unroll
        for (int cf = 0; cf < 8; cf++) {
            int col = wc * 64 + cf * 8 + 2 * t4;
            float bx = sb1[col], by = sb1[col + 1];
            if (r1 < NN)
                *reinterpret_cast<float2*>(&g_h1[(size_t)r1 * 128 + col]) = make_float2(
                    fmaxf(fmaf(c[rf][cf][0], nd1, bx), 0.f),
                    fmaxf(fmaf(c[rf][cf][1], nd1, by), 0.f));
            if (r2 < NN)
                *reinterpret_cast<float2*>(&g_h1[(size_t)r2 * 128 + col]) = make_float2(
                    fmaxf(fmaf(c[rf][cf][2], nd2, bx), 0.f),
                    fmaxf(fmaf(c[rf][cf][3], nd2, by), 0.f));
        }
    }
}

// ---------------- GEMM 2 (tf32 mma.sync): h2 = (h1 * norm_src) @ W2 ----------------
// Block tile 128x64, K=128. 8 warps 4x2: each warp 32r x 32c.
// dyn smem: As[128][132] | Ws[128][68] | sns[128]
#define G2_AS_STRIDE 132
#define G2_WS_STRIDE 68
#define G2_WS_OFF  (128 * G2_AS_STRIDE)
#define G2_NS_OFF  (G2_WS_OFF + 128 * G2_WS_STRIDE)
#define G2_SMEM    ((G2_NS_OFF + 128) * 4)

__global__ void __launch_bounds__(256) k_gemm2_mma(const float* __restrict__ W2) {
    extern __shared__ float sm[];
    float* As  = sm;
    float* Ws  = sm + G2_WS_OFF;
    float* sns = sm + G2_NS_OFF;

    int tid = threadIdx.x;
    int row0 = blockIdx.x * 128;

    if (tid < 128) {
        int row = row0 + tid;
        sns[tid] = (row < NN) ? g_norm_src[row] : 0.f;
    }
    __syncthreads();

    // A tile: 128x128, scaled by norm_src, tf32-rounded
    #pragma unroll
    for (int it = 0; it < 16; it++) {
        int idx4 = tid + it * 256;           // [0,4096)
        int r = idx4 >> 5, c4 = idx4 & 31;
        float4 v = make_float4(0.f, 0.f, 0.f, 0.f);
        int row = row0 + r;
        if (row < NN) v = *reinterpret_cast<const float4*>(&g_h1[(size_t)row * 128 + c4 * 4]);
        float s = sns[r];
        float* p = &As[r * G2_AS_STRIDE + c4 * 4];
        p[0] = __uint_as_float(f2tf32(v.x * s)); p[1] = __uint_as_float(f2tf32(v.y * s));
        p[2] = __uint_as_float(f2tf32(v.z * s)); p[3] = __uint_as_float(f2tf32(v.w * s));
    }
    // W tile: 128x64
    #pragma unroll
    for (int it = 0; it < 8; it++) {
        int idx4 = tid + it * 256;           // [0,2048)
        int k = idx4 >> 4, c4 = idx4 & 15;
        float4 v = *reinterpret_cast<const float4*>(&W2[(size_t)k * 64 + c4 * 4]);
        float* p = &Ws[k * G2_WS_STRIDE + c4 * 4];
        p[0] = __uint_as_float(f2tf32(v.x)); p[1] = __uint_as_float(f2tf32(v.y));
        p[2] = __uint_as_float(f2tf32(v.z)); p[3] = __uint_as_float(f2tf32(v.w));
    }
    __syncthreads();

    int w = tid >> 5, lane = tid & 31;
    int wr = w >> 1, wc = w & 1;
    int g = lane >> 2, t4 = lane & 3;

    float c[2][4][4];
    #pragma unroll
    for (int i = 0; i < 2; i++)
        #pragma unroll
        for (int j = 0; j < 4; j++)
            #pragma unroll
            for (int q = 0; q < 4; q++) c[i][j][q] = 0.f;

    const uint32_t* Au = reinterpret_cast<const uint32_t*>(As);
    const uint32_t* Wu = reinterpret_cast<const uint32_t*>(Ws);

    #pragma unroll
    for (int ks = 0; ks < 16; ks++) {
        int kb = ks * 8;
        uint32_t a[2][4];
        #pragma unroll
        for (int rf = 0; rf < 2; rf++) {
            int R = wr * 32 + rf * 16;
            a[rf][0] = Au[(R + g) * G2_AS_STRIDE + kb + t4];
            a[rf][1] = Au[(R + 8 + g) * G2_AS_STRIDE + kb + t4];
            a[rf][2] = Au[(R + g) * G2_AS_STRIDE + kb + 4 + t4];
            a[rf][3] = Au[(R + 8 + g) * G2_AS_STRIDE + kb + 4 + t4];
        }
        #pragma unroll
        for (int cf = 0; cf < 4; cf++) {
            int C = wc * 32 + cf * 8 + g;
            uint32_t b0 = Wu[(kb + t4) * G2_WS_STRIDE + C];
            uint32_t b1r = Wu[(kb + 4 + t4) * G2_WS_STRIDE + C];
            #pragma unroll
            for (int rf = 0; rf < 2; rf++)
                MMA_TF32(c[rf][cf][0], c[rf][cf][1], c[rf][cf][2], c[rf][cf][3],
                         a[rf][0], a[rf][1], a[rf][2], a[rf][3], b0, b1r);
        }
    }

    #pragma unroll
    for (int rf = 0; rf < 2; rf++) {
        int r1 = row0 + wr * 32 + rf * 16 + g;
        int r2 = r1 + 8;
        #pragma unroll
        for (int cf = 0; cf < 4; cf++) {
            int col = wc * 32 + cf * 8 + 2 * t4;
            if (r1 < NN)
                *reinterpret_cast<float2*>(&g_h2[(size_t)r1 * 64 + col]) =
                    make_float2(c[rf][cf][0], c[rf][cf][1]);
            if (r2 < NN)
                *reinterpret_cast<float2*>(&g_h2[(size_t)r2 * 64 + col]) =
                    make_float2(c[rf][cf][2], c[rf][cf][3]);
        }
    }
}

// ---------------- launch ----------------
extern "C" void kernel_launch(void* const* d_in, const int* in_sizes, int n_in,
                              void* d_out, int out_size) {
    const float* x   = (const float*)d_in[0];
    const float* W1  = (const float*)d_in[1];
    const float* b1  = (const float*)d_in[2];
    const float* W2  = (const float*)d_in[3];
    const float* b2  = (const float*)d_in[4];
    const int*   src = (const int*)d_in[5];
    const int*   dst = (const int*)d_in[6];
    float* out = (float*)d_out;

    cudaFuncSetAttribute(k_gemm1_mma, cudaFuncAttributeMaxDynamicSharedMemorySize, G1_SMEM);
    cudaFuncSetAttribute(k_gemm2_mma, cudaFuncAttributeMaxDynamicSharedMemorySize, G2_SMEM);

    k_zero<<<(NN + 255) / 256, 256>>>();
    k_degree<<<(EE + 255) / 256, 256>>>(src, dst);
    k_scan_blk<<<SCAN_BLK, 1024>>>();
    k_scan_add<<<(NN + 255) / 256, 256>>>();
    k_scatter<<<(EE + 255) / 256, 256>>>(src, dst);

    int ntiles = (NN + 127) / 128;   // 391
    k_agg<true><<<NN, 64>>>(x, nullptr, nullptr);
    k_gemm1_mma<<<ntiles, 256, G1_SMEM>>>(W1, b1);
    k_gemm2_mma<<<ntiles, 256, G2_SMEM>>>(W2);
    k_agg<false><<<NN, 64>>>(nullptr, b2, out);
}

// round 8
// speedup vs baseline: 2.4369x; 1.2277x over previous
#include <cuda_runtime.h>
#include <cuda_bf16.h>
#include <cstdint>

#define NN 50000
#define EE 800000
#define F_IN 64
#define F_HID 128
#define F_OUT 64
#define SCAN_BLK ((NN + 1023) / 1024)   // 49

// ---------------- device scratch (no allocations allowed) ----------------
__device__ __align__(16) int   g_outdeg[NN];
__device__ __align__(16) int   g_indeg[NN];
__device__ __align__(16) int   g_cursor[NN];
__device__ __align__(16) int   g_rowptr[NN + 1];
__device__ __align__(16) int   g_esrc[EE];
__device__ __align__(16) int   g_bsum[SCAN_BLK];
__device__ __align__(16) float g_norm_src[NN];
__device__ __align__(16) float g_norm_dst[NN];
__device__ __align__(16) float g_agg1[(size_t)NN * F_IN];
__device__ __align__(16) float g_h1[(size_t)NN * F_HID];
__device__ __align__(16) float g_h2[(size_t)NN * F_OUT];

__device__ __forceinline__ uint32_t f2tf32(float v) {
    uint32_t u;
    asm("cvt.rna.tf32.f32 %0, %1;" : "=r"(u) : "f"(v));
    return u;
}

#define MMA_TF32(c0, c1, c2, c3, a0, a1, a2, a3, b0, b1) \
    asm volatile("mma.sync.aligned.m16n8k8.row.col.f32.tf32.tf32.f32 " \
        "{%0,%1,%2,%3}, {%4,%5,%6,%7}, {%8,%9}, {%0,%1,%2,%3};" \
        : "+f"(c0), "+f"(c1), "+f"(c2), "+f"(c3) \
        : "r"(a0), "r"(a1), "r"(a2), "r"(a3), "r"(b0), "r"(b1))

// ---------------- graph preprocessing ----------------
__global__ void k_zero() {
    int i = blockIdx.x * blockDim.x + threadIdx.x;
    if (i < NN) { g_outdeg[i] = 0; g_indeg[i] = 0; }
}

__global__ void k_degree(const int* __restrict__ src, const int* __restrict__ dst) {
    int e = blockIdx.x * blockDim.x + threadIdx.x;
    if (e < EE) {
        atomicAdd(&g_outdeg[src[e]], 1);
        atomicAdd(&g_indeg[dst[e]], 1);
    }
}

// per-block inclusive scan of indeg; norms fused
__global__ void k_scan_blk() {
    __shared__ int sh[1024];
    int t = threadIdx.x;
    int i = blockIdx.x * 1024 + t;
    int deg = (i < NN) ? g_indeg[i] : 0;
    if (i < NN) {
        g_norm_dst[i] = rsqrtf((float)max(deg, 1));
        g_norm_src[i] = rsqrtf((float)max(g_outdeg[i], 1));
    }
    sh[t] = deg;
    __syncthreads();
    #pragma unroll
    for (int off = 1; off < 1024; off <<= 1) {
        int x = (t >= off) ? sh[t - off] : 0;
        __syncthreads();
        sh[t] += x;
        __syncthreads();
    }
    if (i < NN) g_rowptr[i + 1] = sh[t];
    if (t == 1023) g_bsum[blockIdx.x] = sh[1023];
}

// add block offsets (warp 0 sums its block's bsum prefix) + cursor init, 1024-wide
__global__ void k_scan_add() {
    __shared__ int off;
    int t = threadIdx.x;
    int i = blockIdx.x * 1024 + t;
    if (t < 32) {
        int s = 0;
        for (int b = t; b < blockIdx.x; b += 32) s += g_bsum[b];
        #pragma unroll
        for (int o = 16; o > 0; o >>= 1) s += __shfl_down_sync(0xFFFFFFFFu, s, o);
        if (t == 0) off = s;
    }
    __syncthreads();
    if (i < NN) {
        int v = g_rowptr[i + 1] + off;
        g_rowptr[i + 1] = v;
        if (i + 1 < NN) g_cursor[i + 1] = v;
        if (i == 0) { g_rowptr[0] = 0; g_cursor[0] = 0; }
    }
}

__global__ void k_scatter(const int* __restrict__ src, const int* __restrict__ dst) {
    int e = blockIdx.x * blockDim.x + threadIdx.x;
    if (e < EE) {
        int pos = atomicAdd(&g_cursor[dst[e]], 1);
        g_esrc[pos] = src[e];
    }
}

// ---------------- aggregation: one warp per destination node, float4 lanes ----------------
// Lanes [0,16) = edge slot 0, lanes [16,32) = edge slot 1: 2 edges in flight per warp.
// LAYER1: feat = x (arg), scale gathered row by norm_src[u], out = g_agg1 (internal)
// !LAYER1: feat = g_h2 (internal), out = arg, epilogue acc*norm_dst + bias
template <bool LAYER1>
__global__ void __launch_bounds__(256) k_agg(const float* __restrict__ feat_in,
                                             const float* __restrict__ bias,
                                             float* __restrict__ out_arg) {
    const float4* __restrict__ feat = LAYER1
        ? reinterpret_cast<const float4*>(feat_in)
        : reinterpret_cast<const float4*>(g_h2);
    int n = blockIdx.x * 8 + (threadIdx.x >> 5);   // grid*8 == NN exactly
    int lane = threadIdx.x & 31;
    int slot = lane >> 4;
    int fl   = lane & 15;

    int s = g_rowptr[n], e = g_rowptr[n + 1];
    float4 acc = make_float4(0.f, 0.f, 0.f, 0.f);
    #pragma unroll 4
    for (int j = s + slot; j < e; j += 2) {
        int u = g_esrc[j];
        float4 v = feat[(size_t)u * 16 + fl];
        if (LAYER1) {
            float sc = g_norm_src[u];
            acc.x = fmaf(v.x, sc, acc.x); acc.y = fmaf(v.y, sc, acc.y);
            acc.z = fmaf(v.z, sc, acc.z); acc.w = fmaf(v.w, sc, acc.w);
        } else {
            acc.x += v.x; acc.y += v.y; acc.z += v.z; acc.w += v.w;
        }
    }
    // combine the two slots
    acc.x += __shfl_down_sync(0xFFFFFFFFu, acc.x, 16);
    acc.y += __shfl_down_sync(0xFFFFFFFFu, acc.y, 16);
    acc.z += __shfl_down_sync(0xFFFFFFFFu, acc.z, 16);
    acc.w += __shfl_down_sync(0xFFFFFFFFu, acc.w, 16);

    if (slot == 0) {
        if (LAYER1) {
            reinterpret_cast<float4*>(g_agg1)[(size_t)n * 16 + fl] = acc;
        } else {
            float nd = g_norm_dst[n];
            float4 bv = reinterpret_cast<const float4*>(bias)[fl];
            float4 o;
            o.x = fmaf(acc.x, nd, bv.x); o.y = fmaf(acc.y, nd, bv.y);
            o.z = fmaf(acc.z, nd, bv.z); o.w = fmaf(acc.w, nd, bv.w);
            reinterpret_cast<float4*>(out_arg)[(size_t)n * 16 + fl] = o;
        }
    }
}

// ---------------- GEMM 1 (tf32 mma.sync): h1 = relu((agg1 @ W1)*nd + b1) ----------------
// Block tile 128x128, K=64. 8 warps as 4(row)x2(col): each warp 32r x 64c.
#define G1_AS_STRIDE 76
#define G1_WS_STRIDE 132
#define G1_WS_OFF  (128 * G1_AS_STRIDE)
#define G1_B1_OFF  (G1_WS_OFF + 64 * G1_WS_STRIDE)
#define G1_SMEM    ((G1_B1_OFF + 128) * 4)

__global__ void __launch_bounds__(256) k_gemm1_mma(const float* __restrict__ W1,
                                                   const float* __restrict__ b1) {
    extern __shared__ float sm[];
    float* As  = sm;
    float* Ws  = sm + G1_WS_OFF;
    float* sb1 = sm + G1_B1_OFF;

    int tid = threadIdx.x;
    int row0 = blockIdx.x * 128;

    #pragma unroll
    for (int it = 0; it < 8; it++) {
        int idx4 = tid + it * 256;
        int r = idx4 >> 4, c4 = idx4 & 15;
        float4 v = make_float4(0.f, 0.f, 0.f, 0.f);
        int row = row0 + r;
        if (row < NN) v = *reinterpret_cast<const float4*>(&g_agg1[(size_t)row * 64 + c4 * 4]);
        float* p = &As[r * G1_AS_STRIDE + c4 * 4];
        p[0] = __uint_as_float(f2tf32(v.x)); p[1] = __uint_as_float(f2tf32(v.y));
        p[2] = __uint_as_float(f2tf32(v.z)); p[3] = __uint_as_float(f2tf32(v.w));
    }
    #pragma unroll
    for (int it = 0; it < 8; it++) {
        int idx4 = tid + it * 256;
        int k = idx4 >> 5, c4 = idx4 & 31;
        float4 v = *reinterpret_cast<const float4*>(&W1[(size_t)k * 128 + c4 * 4]);
        float* p = &Ws[k * G1_WS_STRIDE + c4 * 4];
        p[0] = __uint_as_float(f2tf32(v.x)); p[1] = __uint_as_float(f2tf32(v.y));
        p[2] = __uint_as_float(f2tf32(v.z)); p[3] = __uint_as_float(f2tf32(v.w));
    }
    if (tid < 128) sb1[tid] = b1[tid];
    __syncthreads();

    int w = tid >> 5, lane = tid & 31;
    int wr = w >> 1, wc = w & 1;
    int g = lane >> 2, t4 = lane & 3;

    float c[2][8][4];
    #pragma unroll
    for (int i = 0; i < 2; i++)
        #pragma unroll
        for (int j = 0; j < 8; j++)
            #pragma unroll
            for (int q = 0; q < 4; q++) c[i][j][q] = 0.f;

    const uint32_t* Au = reinterpret_cast<const uint32_t*>(As);
    const uint32_t* Wu = reinterpret_cast<const uint32_t*>(Ws);

    #pragma unroll
    for (int ks = 0; ks < 8; ks++) {
        int kb = ks * 8;
        uint32_t a[2][4];
        #pragma unroll
        for (int rf = 0; rf < 2; rf++) {
            int R = wr * 32 + rf * 16;
            a[rf][0] = Au[(R + g) * G1_AS_STRIDE + kb + t4];
            a[rf][1] = Au[(R + 8 + g) * G1_AS_STRIDE + kb + t4];
            a[rf][2] = Au[(R + g) * G1_AS_STRIDE + kb + 4 + t4];
            a[rf][3] = Au[(R + 8 + g) * G1_AS_STRIDE + kb + 4 + t4];
        }
        #pragma unroll
        for (int cf = 0; cf < 8; cf++) {
            int C = wc * 64 + cf * 8 + g;
            uint32_t b0 = Wu[(kb + t4) * G1_WS_STRIDE + C];
            uint32_t b1r = Wu[(kb + 4 + t4) * G1_WS_STRIDE + C];
            #pragma unroll
            for (int rf = 0; rf < 2; rf++)
                MMA_TF32(c[rf][cf][0], c[rf][cf][1], c[rf][cf][2], c[rf][cf][3],
                         a[rf][0], a[rf][1], a[rf][2], a[rf][3], b0, b1r);
        }
    }

    #pragma unroll
    for (int rf = 0; rf < 2; rf++) {
        int r1 = row0 + wr * 32 + rf * 16 + g;
        int r2 = r1 + 8;
        float nd1 = (r1 < NN) ? g_norm_dst[r1] : 0.f;
        float nd2 = (r2 < NN) ? g_norm_dst[r2] : 0.f;
        #pragma unroll
        for (int cf = 0; cf < 8; cf++) {
            int col = wc * 64 + cf * 8 + 2 * t4;
            float bx = sb1[col], by = sb1[col + 1];
            if (r1 < NN)
                *reinterpret_cast<float2*>(&g_h1[(size_t)r1 * 128 + col]) = make_float2(
                    fmaxf(fmaf(c[rf][cf][0], nd1, bx), 0.f),
                    fmaxf(fmaf(c[rf][cf][1], nd1, by), 0.f));
            if (r2 < NN)
                *reinterpret_cast<float2*>(&g_h1[(size_t)r2 * 128 + col]) = make_float2(
                    fmaxf(fmaf(c[rf][cf][2], nd2, bx), 0.f),
                    fmaxf(fmaf(c[rf][cf][3], nd2, by), 0.f));
        }
    }
}

// ---------------- GEMM 2 (tf32 mma.sync): h2 = (h1 * norm_src) @ W2 ----------------
#define G2_AS_STRIDE 132
#define G2_WS_STRIDE 68
#define G2_WS_OFF  (128 * G2_AS_STRIDE)
#define G2_NS_OFF  (G2_WS_OFF + 128 * G2_WS_STRIDE)
#define G2_SMEM    ((G2_NS_OFF + 128) * 4)

__global__ void __launch_bounds__(256) k_gemm2_mma(const float* __restrict__ W2) {
    extern __shared__ float sm[];
    float* As  = sm;
    float* Ws  = sm + G2_WS_OFF;
    float* sns = sm + G2_NS_OFF;

    int tid = threadIdx.x;
    int row0 = blockIdx.x * 128;

    if (tid < 128) {
        int row = row0 + tid;
        sns[tid] = (row < NN) ? g_norm_src[row] : 0.f;
    }
    __syncthreads();

    #pragma unroll
    for (int it = 0; it < 16; it++) {
        int idx4 = tid + it * 256;
        int r = idx4 >> 5, c4 = idx4 & 31;
        float4 v = make_float4(0.f, 0.f, 0.f, 0.f);
        int row = row0 + r;
        if (row < NN) v = *reinterpret_cast<const float4*>(&g_h1[(size_t)row * 128 + c4 * 4]);
        float s = sns[r];
        float* p = &As[r * G2_AS_STRIDE + c4 * 4];
        p[0] = __uint_as_float(f2tf32(v.x * s)); p[1] = __uint_as_float(f2tf32(v.y * s));
        p[2] = __uint_as_float(f2tf32(v.z * s)); p[3] = __uint_as_float(f2tf32(v.w * s));
    }
    #pragma unroll
    for (int it = 0; it < 8; it++) {
        int idx4 = tid + it * 256;
        int k = idx4 >> 4, c4 = idx4 & 15;
        float4 v = *reinterpret_cast<const float4*>(&W2[(size_t)k * 64 + c4 * 4]);
        float* p = &Ws[k * G2_WS_STRIDE + c4 * 4];
        p[0] = __uint_as_float(f2tf32(v.x)); p[1] = __uint_as_float(f2tf32(v.y));
        p[2] = __uint_as_float(f2tf32(v.z)); p[3] = __uint_as_float(f2tf32(v.w));
    }
    __syncthreads();

    int w = tid >> 5, lane = tid & 31;
    int wr = w >> 1, wc = w & 1;
    int g = lane >> 2, t4 = lane & 3;

    float c[2][4][4];
    #pragma unroll
    for (int i = 0; i < 2; i++)
        #pragma unroll
        for (int j = 0; j < 4; j++)
            #pragma unroll
            for (int q = 0; q < 4; q++) c[i][j][q] = 0.f;

    const uint32_t* Au = reinterpret_cast<const uint32_t*>(As);
    const uint32_t* Wu = reinterpret_cast<const uint32_t*>(Ws);

    #pragma unroll
    for (int ks = 0; ks < 16; ks++) {
        int kb = ks * 8;
        uint32_t a[2][4];
        #pragma unroll
        for (int rf = 0; rf < 2; rf++) {
            int R = wr * 32 + rf * 16;
            a[rf][0] = Au[(R + g) * G2_AS_STRIDE + kb + t4];
            a[rf][1] = Au[(R + 8 + g) * G2_AS_STRIDE + kb + t4];
            a[rf][2] = Au[(R + g) * G2_AS_STRIDE + kb + 4 + t4];
            a[rf][3] = Au[(R + 8 + g) * G2_AS_STRIDE + kb + 4 + t4];
        }
        #pragma unroll
        for (int cf = 0; cf < 4; cf++) {
            int C = wc * 32 + cf * 8 + g;
            uint32_t b0 = Wu[(kb + t4) * G2_WS_STRIDE + C];
            uint32_t b1r = Wu[(kb + 4 + t4) * G2_WS_STRIDE + C];
            #pragma unroll
            for (int rf = 0; rf < 2; rf++)
                MMA_TF32(c[rf][cf][0], c[rf][cf][1], c[rf][cf][2], c[rf][cf][3],
                         a[rf][0], a[rf][1], a[rf][2], a[rf][3], b0, b1r);
        }
    }

    #pragma unroll
    for (int rf = 0; rf < 2; rf++) {
        int r1 = row0 + wr * 32 + rf * 16 + g;
        int r2 = r1 + 8;
        #pragma unroll
        for (int cf = 0; cf < 4; cf++) {
            int col = wc * 32 + cf * 8 + 2 * t4;
            if (r1 < NN)
                *reinterpret_cast<float2*>(&g_h2[(size_t)r1 * 64 + col]) =
                    make_float2(c[rf][cf][0], c[rf][cf][1]);
            if (r2 < NN)
                *reinterpret_cast<float2*>(&g_h2[(size_t)r2 * 64 + col]) =
                    make_float2(c[rf][cf][2], c[rf][cf][3]);
        }
    }
}

// ---------------- launch ----------------
extern "C" void kernel_launch(void* const* d_in, const int* in_sizes, int n_in,
                              void* d_out, int out_size) {
    const float* x   = (const float*)d_in[0];
    const float* W1  = (const float*)d_in[1];
    const float* b1  = (const float*)d_in[2];
    const float* W2  = (const float*)d_in[3];
    const float* b2  = (const float*)d_in[4];
    const int*   src = (const int*)d_in[5];
    const int*   dst = (const int*)d_in[6];
    float* out = (float*)d_out;

    cudaFuncSetAttribute(k_gemm1_mma, cudaFuncAttributeMaxDynamicSharedMemorySize, G1_SMEM);
    cudaFuncSetAttribute(k_gemm2_mma, cudaFuncAttributeMaxDynamicSharedMemorySize, G2_SMEM);

    k_zero<<<(NN + 255) / 256, 256>>>();
    k_degree<<<(EE + 255) / 256, 256>>>(src, dst);
    k_scan_blk<<<SCAN_BLK, 1024>>>();
    k_scan_add<<<SCAN_BLK, 1024>>>();
    k_scatter<<<(EE + 255) / 256, 256>>>(src, dst);

    int ntiles = (NN + 127) / 128;   // 391
    k_agg<true><<<NN / 8, 256>>>(x, nullptr, nullptr);          // 6250 blocks, 1 warp/node
    k_gemm1_mma<<<ntiles, 256, G1_SMEM>>>(W1, b1);
    k_gemm2_mma<<<ntiles, 256, G2_SMEM>>>(W2);
    k_agg<false><<<NN / 8, 256>>>(nullptr, b2, out);
}

// round 9
// speedup vs baseline: 2.6417x; 1.0840x over previous
#include <cuda_runtime.h>
#include <cuda_fp16.h>
#include <cstdint>

#define NN 50000
#define EE 800000
#define SCAN_BLK ((NN + 1023) / 1024)   // 49

// ---------------- device scratch (no allocations allowed) ----------------
__device__ __align__(16) int    g_outdeg[NN];
__device__ __align__(16) int    g_indeg[NN];
__device__ __align__(16) int    g_cursor[NN];
__device__ __align__(16) int    g_rowptr[NN + 1];
__device__ __align__(16) int    g_esrc[EE];
__device__ __align__(16) int    g_bsum[SCAN_BLK];
__device__ __align__(16) float  g_norm_src[NN];
__device__ __align__(16) float  g_norm_dst[NN];
__device__ __align__(16) __half g_x16[(size_t)NN * 64];    // x in fp16
__device__ __align__(16) __half g_agg1[(size_t)NN * 64];   // layer-1 aggregate, fp16
__device__ __align__(16) __half g_h1[(size_t)NN * 128];    // relu output, fp16
__device__ __align__(16) __half g_h2[(size_t)NN * 64];     // layer-2 pre-agg, fp16

__device__ __forceinline__ uint32_t f2tf32(float v) {
    uint32_t u;
    asm("cvt.rna.tf32.f32 %0, %1;" : "=r"(u) : "f"(v));
    return u;
}

#define MMA_TF32(c0, c1, c2, c3, a0, a1, a2, a3, b0, b1) \
    asm volatile("mma.sync.aligned.m16n8k8.row.col.f32.tf32.tf32.f32 " \
        "{%0,%1,%2,%3}, {%4,%5,%6,%7}, {%8,%9}, {%0,%1,%2,%3};" \
        : "+f"(c0), "+f"(c1), "+f"(c2), "+f"(c3) \
        : "r"(a0), "r"(a1), "r"(a2), "r"(a3), "r"(b0), "r"(b1))

// unpack uint4 (8 halves) -> 8 floats
__device__ __forceinline__ void h8_to_f8(uint4 raw, float* f) {
    float2 p;
    p = __half22float2(*reinterpret_cast<__half2*>(&raw.x)); f[0] = p.x; f[1] = p.y;
    p = __half22float2(*reinterpret_cast<__half2*>(&raw.y)); f[2] = p.x; f[3] = p.y;
    p = __half22float2(*reinterpret_cast<__half2*>(&raw.z)); f[4] = p.x; f[5] = p.y;
    p = __half22float2(*reinterpret_cast<__half2*>(&raw.w)); f[6] = p.x; f[7] = p.y;
}

// ---------------- preprocessing ----------------
// convert x -> fp16 (each thread: 8 floats) + zero degree counters
__global__ void k_convzero(const float* __restrict__ x) {
    int i = blockIdx.x * blockDim.x + threadIdx.x;   // [0, NN*64/8)
    if (i < NN * 8) {
        const float4* xp = reinterpret_cast<const float4*>(x) + (size_t)i * 2;
        float4 a = xp[0], b = xp[1];
        uint4 o;
        *reinterpret_cast<__half2*>(&o.x) = __floats2half2_rn(a.x, a.y);
        *reinterpret_cast<__half2*>(&o.y) = __floats2half2_rn(a.z, a.w);
        *reinterpret_cast<__half2*>(&o.z) = __floats2half2_rn(b.x, b.y);
        *reinterpret_cast<__half2*>(&o.w) = __floats2half2_rn(b.z, b.w);
        reinterpret_cast<uint4*>(g_x16)[i] = o;
    }
    if (i < NN) { g_outdeg[i] = 0; g_indeg[i] = 0; }
}

__global__ void k_degree(const int* __restrict__ src, const int* __restrict__ dst) {
    int e = blockIdx.x * blockDim.x + threadIdx.x;
    if (e < EE) {
        atomicAdd(&g_outdeg[src[e]], 1);
        atomicAdd(&g_indeg[dst[e]], 1);
    }
}

// per-block inclusive scan of indeg; norms fused
__global__ void k_scan_blk() {
    __shared__ int sh[1024];
    int t = threadIdx.x;
    int i = blockIdx.x * 1024 + t;
    int deg = (i < NN) ? g_indeg[i] : 0;
    if (i < NN) {
        g_norm_dst[i] = rsqrtf((float)max(deg, 1));
        g_norm_src[i] = rsqrtf((float)max(g_outdeg[i], 1));
    }
    sh[t] = deg;
    __syncthreads();
    #pragma unroll
    for (int off = 1; off < 1024; off <<= 1) {
        int x = (t >= off) ? sh[t - off] : 0;
        __syncthreads();
        sh[t] += x;
        __syncthreads();
    }
    if (i < NN) g_rowptr[i + 1] = sh[t];
    if (t == 1023) g_bsum[blockIdx.x] = sh[1023];
}

// add block offsets + cursor init
__global__ void k_scan_add() {
    __shared__ int off;
    int t = threadIdx.x;
    int i = blockIdx.x * 1024 + t;
    if (t < 32) {
        int s = 0;
        for (int b = t; b < blockIdx.x; b += 32) s += g_bsum[b];
        #pragma unroll
        for (int o = 16; o > 0; o >>= 1) s += __shfl_down_sync(0xFFFFFFFFu, s, o);
        if (t == 0) off = s;
    }
    __syncthreads();
    if (i < NN) {
        int v = g_rowptr[i + 1] + off;
        g_rowptr[i + 1] = v;
        if (i + 1 < NN) g_cursor[i + 1] = v;
        if (i == 0) { g_rowptr[0] = 0; g_cursor[0] = 0; }
    }
}

__global__ void k_scatter(const int* __restrict__ src, const int* __restrict__ dst) {
    int e = blockIdx.x * blockDim.x + threadIdx.x;
    if (e < EE) {
        int pos = atomicAdd(&g_cursor[dst[e]], 1);
        g_esrc[pos] = src[e];
    }
}

// ---------------- aggregation: one warp per node, 4 edge slots x 8 lanes x 16B ----------------
// LAYER1: feat = g_x16, scale by norm_src[u], out -> g_agg1 (fp16)
// !LAYER1: feat = g_h2,  epilogue acc*norm_dst + bias -> out_arg (fp32)
template <bool LAYER1>
__global__ void __launch_bounds__(256) k_agg(const float* __restrict__ bias,
                                             float* __restrict__ out_arg) {
    const uint4* __restrict__ feat = LAYER1
        ? reinterpret_cast<const uint4*>(g_x16)
        : reinterpret_cast<const uint4*>(g_h2);
    int n = blockIdx.x * 8 + (threadIdx.x >> 5);   // grid*8 == NN
    int lane = threadIdx.x & 31;
    int slot = lane >> 3;        // 4 slots
    int fl   = lane & 7;         // 8 lanes/slot, 8 halves each

    int s = g_rowptr[n], e = g_rowptr[n + 1];
    float acc[8] = {0.f, 0.f, 0.f, 0.f, 0.f, 0.f, 0.f, 0.f};
    #pragma unroll 2
    for (int j = s + slot; j < e; j += 4) {
        int u = g_esrc[j];
        uint4 raw = feat[(size_t)u * 8 + fl];     // 64 halves/row = 8 uint4
        float f[8];
        h8_to_f8(raw, f);
        if (LAYER1) {
            float sc = g_norm_src[u];
            #pragma unroll
            for (int k = 0; k < 8; k++) acc[k] = fmaf(f[k], sc, acc[k]);
        } else {
            #pragma unroll
            for (int k = 0; k < 8; k++) acc[k] += f[k];
        }
    }
    // combine 4 slots
    #pragma unroll
    for (int o = 16; o >= 8; o >>= 1)
        #pragma unroll
        for (int k = 0; k < 8; k++)
            acc[k] += __shfl_down_sync(0xFFFFFFFFu, acc[k], o);

    if (slot == 0) {
        if (LAYER1) {
            uint4 o;
            *reinterpret_cast<__half2*>(&o.x) = __floats2half2_rn(acc[0], acc[1]);
            *reinterpret_cast<__half2*>(&o.y) = __floats2half2_rn(acc[2], acc[3]);
            *reinterpret_cast<__half2*>(&o.z) = __floats2half2_rn(acc[4], acc[5]);
            *reinterpret_cast<__half2*>(&o.w) = __floats2half2_rn(acc[6], acc[7]);
            reinterpret_cast<uint4*>(g_agg1)[(size_t)n * 8 + fl] = o;
        } else {
            float nd = g_norm_dst[n];
            float4 b0 = reinterpret_cast<const float4*>(bias)[fl * 2];
            float4 b1 = reinterpret_cast<const float4*>(bias)[fl * 2 + 1];
            float* op = out_arg + (size_t)n * 64 + fl * 8;
            *reinterpret_cast<float4*>(op) = make_float4(
                fmaf(acc[0], nd, b0.x), fmaf(acc[1], nd, b0.y),
                fmaf(acc[2], nd, b0.z), fmaf(acc[3], nd, b0.w));
            *reinterpret_cast<float4*>(op + 4) = make_float4(
                fmaf(acc[4], nd, b1.x), fmaf(acc[5], nd, b1.y),
                fmaf(acc[6], nd, b1.z), fmaf(acc[7], nd, b1.w));
        }
    }
}

// ---------------- GEMM 1 (tf32 mma.sync): h1 = relu((agg1 @ W1)*nd + b1) ----------------
#define G1_AS_STRIDE 76
#define G1_WS_STRIDE 132
#define G1_WS_OFF  (128 * G1_AS_STRIDE)
#define G1_B1_OFF  (G1_WS_OFF + 64 * G1_WS_STRIDE)
#define G1_SMEM    ((G1_B1_OFF + 128) * 4)

__global__ void __launch_bounds__(256) k_gemm1_mma(const float* __restrict__ W1,
                                                   const float* __restrict__ b1) {
    extern __shared__ float sm[];
    float* As  = sm;
    float* Ws  = sm + G1_WS_OFF;
    float* sb1 = sm + G1_B1_OFF;

    int tid = threadIdx.x;
    int row0 = blockIdx.x * 128;

    // A tile: 128 rows x 64 halves (8 uint4/row)
    #pragma unroll
    for (int it = 0; it < 4; it++) {
        int idx = tid + it * 256;            // [0,1024)
        int r = idx >> 3, c8 = idx & 7;
        int row = row0 + r;
        float f[8] = {0.f, 0.f, 0.f, 0.f, 0.f, 0.f, 0.f, 0.f};
        if (row < NN) {
            uint4 raw = reinterpret_cast<const uint4*>(g_agg1)[(size_t)row * 8 + c8];
            h8_to_f8(raw, f);
        }
        float* p = &As[r * G1_AS_STRIDE + c8 * 8];
        #pragma unroll
        for (int k = 0; k < 8; k++) p[k] = __uint_as_float(f2tf32(f[k]));
    }
    // W tile: 64x128 fp32
    #pragma unroll
    for (int it = 0; it < 8; it++) {
        int idx4 = tid + it * 256;
        int k = idx4 >> 5, c4 = idx4 & 31;
        float4 v = *reinterpret_cast<const float4*>(&W1[(size_t)k * 128 + c4 * 4]);
        float* p = &Ws[k * G1_WS_STRIDE + c4 * 4];
        p[0] = __uint_as_float(f2tf32(v.x)); p[1] = __uint_as_float(f2tf32(v.y));
        p[2] = __uint_as_float(f2tf32(v.z)); p[3] = __uint_as_float(f2tf32(v.w));
    }
    if (tid < 128) sb1[tid] = b1[tid];
    __syncthreads();

    int w = tid >> 5, lane = tid & 31;
    int wr = w >> 1, wc = w & 1;
    int g = lane >> 2, t4 = lane & 3;

    float c[2][8][4];
    #pragma unroll
    for (int i = 0; i < 2; i++)
        #pragma unroll
        for (int j = 0; j < 8; j++)
            #pragma unroll
            for (int q = 0; q < 4; q++) c[i][j][q] = 0.f;

    const uint32_t* Au = reinterpret_cast<const uint32_t*>(As);
    const uint32_t* Wu = reinterpret_cast<const uint32_t*>(Ws);

    #pragma unroll
    for (int ks = 0; ks < 8; ks++) {
        int kb = ks * 8;
        uint32_t a[2][4];
        #pragma unroll
        for (int rf = 0; rf < 2; rf++) {
            int R = wr * 32 + rf * 16;
            a[rf][0] = Au[(R + g) * G1_AS_STRIDE + kb + t4];
            a[rf][1] = Au[(R + 8 + g) * G1_AS_STRIDE + kb + t4];
            a[rf][2] = Au[(R + g) * G1_AS_STRIDE + kb + 4 + t4];
            a[rf][3] = Au[(R + 8 + g) * G1_AS_STRIDE + kb + 4 + t4];
        }
        #pragma unroll
        for (int cf = 0; cf < 8; cf++) {
            int C = wc * 64 + cf * 8 + g;
            uint32_t b0 = Wu[(kb + t4) * G1_WS_STRIDE + C];
            uint32_t b1r = Wu[(kb + 4 + t4) * G1_WS_STRIDE + C];
            #pragma unroll
            for (int rf = 0; rf < 2; rf++)
                MMA_TF32(c[rf][cf][0], c[rf][cf][1], c[rf][cf][2], c[rf][cf][3],
                         a[rf][0], a[rf][1], a[rf][2], a[rf][3], b0, b1r);
        }
    }

    // epilogue: relu(c*nd + b1) -> g_h1 (fp16, half2 stores)
    #pragma unroll
    for (int rf = 0; rf < 2; rf++) {
        int r1 = row0 + wr * 32 + rf * 16 + g;
        int r2 = r1 + 8;
        float nd1 = (r1 < NN) ? g_norm_dst[r1] : 0.f;
        float nd2 = (r2 < NN) ? g_norm_dst[r2] : 0.f;
        #pragma unroll
        for (int cf = 0; cf < 8; cf++) {
            int col = wc * 64 + cf * 8 + 2 * t4;
            float bx = sb1[col], by = sb1[col + 1];
            if (r1 < NN)
                *reinterpret_cast<__half2*>(&g_h1[(size_t)r1 * 128 + col]) =
                    __floats2half2_rn(fmaxf(fmaf(c[rf][cf][0], nd1, bx), 0.f),
                                      fmaxf(fmaf(c[rf][cf][1], nd1, by), 0.f));
            if (r2 < NN)
                *reinterpret_cast<__half2*>(&g_h1[(size_t)r2 * 128 + col]) =
                    __floats2half2_rn(fmaxf(fmaf(c[rf][cf][2], nd2, bx), 0.f),
                                      fmaxf(fmaf(c[rf][cf][3], nd2, by), 0.f));
        }
    }
}

// ---------------- GEMM 2 (tf32 mma.sync): h2 = (h1 * norm_src) @ W2 ----------------
#define G2_AS_STRIDE 132
#define G2_WS_STRIDE 68
#define G2_WS_OFF  (128 * G2_AS_STRIDE)
#define G2_NS_OFF  (G2_WS_OFF + 128 * G2_WS_STRIDE)
#define G2_SMEM    ((G2_NS_OFF + 128) * 4)

__global__ void __launch_bounds__(256) k_gemm2_mma(const float* __restrict__ W2) {
    extern __shared__ float sm[];
    float* As  = sm;
    float* Ws  = sm + G2_WS_OFF;
    float* sns = sm + G2_NS_OFF;

    int tid = threadIdx.x;
    int row0 = blockIdx.x * 128;

    if (tid < 128) {
        int row = row0 + tid;
        sns[tid] = (row < NN) ? g_norm_src[row] : 0.f;
    }
    __syncthreads();

    // A tile: 128 rows x 128 halves (16 uint4/row), scaled by norm_src
    #pragma unroll
    for (int it = 0; it < 8; it++) {
        int idx = tid + it * 256;            // [0,2048)
        int r = idx >> 4, c8 = idx & 15;
        int row = row0 + r;
        float f[8] = {0.f, 0.f, 0.f, 0.f, 0.f, 0.f, 0.f, 0.f};
        if (row < NN) {
            uint4 raw = reinterpret_cast<const uint4*>(g_h1)[(size_t)row * 16 + c8];
            h8_to_f8(raw, f);
        }
        float s = sns[r];
        float* p = &As[r * G2_AS_STRIDE + c8 * 8];
        #pragma unroll
        for (int k = 0; k < 8; k++) p[k] = __uint_as_float(f2tf32(f[k] * s));
    }
    // W tile: 128x64 fp32
    #pragma unroll
    for (int it = 0; it < 8; it++) {
        int idx4 = tid + it * 256;
        int k = idx4 >> 4, c4 = idx4 & 15;
        float4 v = *reinterpret_cast<const float4*>(&W2[(size_t)k * 64 + c4 * 4]);
        float* p = &Ws[k * G2_WS_STRIDE + c4 * 4];
        p[0] = __uint_as_float(f2tf32(v.x)); p[1] = __uint_as_float(f2tf32(v.y));
        p[2] = __uint_as_float(f2tf32(v.z)); p[3] = __uint_as_float(f2tf32(v.w));
    }
    __syncthreads();

    int w = tid >> 5, lane = tid & 31;
    int wr = w >> 1, wc = w & 1;
    int g = lane >> 2, t4 = lane & 3;

    float c[2][4][4];
    #pragma unroll
    for (int i = 0; i < 2; i++)
        #pragma unroll
        for (int j = 0; j < 4; j++)
            #pragma unroll
            for (int q = 0; q < 4; q++) c[i][j][q] = 0.f;

    const uint32_t* Au = reinterpret_cast<const uint32_t*>(As);
    const uint32_t* Wu = reinterpret_cast<const uint32_t*>(Ws);

    #pragma unroll
    for (int ks = 0; ks < 16; ks++) {
        int kb = ks * 8;
        uint32_t a[2][4];
        #pragma unroll
        for (int rf = 0; rf < 2; rf++) {
            int R = wr * 32 + rf * 16;
            a[rf][0] = Au[(R + g) * G2_AS_STRIDE + kb + t4];
            a[rf][1] = Au[(R + 8 + g) * G2_AS_STRIDE + kb + t4];
            a[rf][2] = Au[(R + g) * G2_AS_STRIDE + kb + 4 + t4];
            a[rf][3] = Au[(R + 8 + g) * G2_AS_STRIDE + kb + 4 + t4];
        }
        #pragma unroll
        for (int cf = 0; cf < 4; cf++) {
            int C = wc * 32 + cf * 8 + g;
            uint32_t b0 = Wu[(kb + t4) * G2_WS_STRIDE + C];
            uint32_t b1r = Wu[(kb + 4 + t4) * G2_WS_STRIDE + C];
            #pragma unroll
            for (int rf = 0; rf < 2; rf++)
                MMA_TF32(c[rf][cf][0], c[rf][cf][1], c[rf][cf][2], c[rf][cf][3],
                         a[rf][0], a[rf][1], a[rf][2], a[rf][3], b0, b1r);
        }
    }

    // epilogue -> g_h2 (fp16)
    #pragma unroll
    for (int rf = 0; rf < 2; rf++) {
        int r1 = row0 + wr * 32 + rf * 16 + g;
        int r2 = r1 + 8;
        #pragma unroll
        for (int cf = 0; cf < 4; cf++) {
            int col = wc * 32 + cf * 8 + 2 * t4;
            if (r1 < NN)
                *reinterpret_cast<__half2*>(&g_h2[(size_t)r1 * 64 + col]) =
                    __floats2half2_rn(c[rf][cf][0], c[rf][cf][1]);
            if (r2 < NN)
                *reinterpret_cast<__half2*>(&g_h2[(size_t)r2 * 64 + col]) =
                    __floats2half2_rn(c[rf][cf][2], c[rf][cf][3]);
        }
    }
}

// ---------------- launch ----------------
extern "C" void kernel_launch(void* const* d_in, const int* in_sizes, int n_in,
                              void* d_out, int out_size) {
    const float* x   = (const float*)d_in[0];
    const float* W1  = (const float*)d_in[1];
    const float* b1  = (const float*)d_in[2];
    const float* W2  = (const float*)d_in[3];
    const float* b2  = (const float*)d_in[4];
    const int*   src = (const int*)d_in[5];
    const int*   dst = (const int*)d_in[6];
    float* out = (float*)d_out;

    cudaFuncSetAttribute(k_gemm1_mma, cudaFuncAttributeMaxDynamicSharedMemorySize, G1_SMEM);
    cudaFuncSetAttribute(k_gemm2_mma, cudaFuncAttributeMaxDynamicSharedMemorySize, G2_SMEM);

    k_convzero<<<(NN * 8 + 255) / 256, 256>>>(x);
    k_degree<<<(EE + 255) / 256, 256>>>(src, dst);
    k_scan_blk<<<SCAN_BLK, 1024>>>();
    k_scan_add<<<SCAN_BLK, 1024>>>();
    k_scatter<<<(EE + 255) / 256, 256>>>(src, dst);

    int ntiles = (NN + 127) / 128;   // 391
    k_agg<true><<<NN / 8, 256>>>(nullptr, nullptr);
    k_gemm1_mma<<<ntiles, 256, G1_SMEM>>>(W1, b1);
    k_gemm2_mma<<<ntiles, 256, G2_SMEM>>>(W2);
    k_agg<false><<<NN / 8, 256>>>(b2, out);
}